// round 14
// baseline (speedup 1.0000x reference)
#include <cuda_runtime.h>
#include <math.h>
#include <stdint.h>

// ---------------------------------------------------------------------------
// Problem constants
// ---------------------------------------------------------------------------
#define BB    2
#define TSEQ  2048
#define DD    1024
#define HH    8
#define KDIM  128
#define VDIM  256
#define KEYD  1024          // H*KDIM
#define VALD  2048          // H*VDIM
#define NTOK  (BB*TSEQ)     // 4096
#define KS    4
#define PS    6144          // packed projection row stride (q|k|v|g)
#define QO    0
#define KO    1024
#define VO    2048
#define GO    4096

// ---------------------------------------------------------------------------
// Scratch arena (device global — no allocation allowed)
// ---------------------------------------------------------------------------
static constexpr size_t OFF_WPACK = 0;                                  // [1024][6144] tf32-rounded
static constexpr size_t OFF_XR    = OFF_WPACK + (size_t)DD * PS;        // [4096][1024] tf32-rounded x
static constexpr size_t OFF_WOR   = OFF_XR    + (size_t)NTOK * DD;      // [2048][1024] tf32-rounded Wo
static constexpr size_t OFF_WABT  = OFF_WOR   + (size_t)VALD * DD;      // [2][8][1024]
static constexpr size_t OFF_PROJ  = OFF_WABT  + (size_t)2 * HH * DD;    // [4096][6144]
static constexpr size_t OFF_QC    = OFF_PROJ  + (size_t)NTOK * PS;      // [4096][1024]
static constexpr size_t OFF_KC    = OFF_QC    + (size_t)NTOK * KEYD;
static constexpr size_t OFF_VC    = OFF_KC    + (size_t)NTOK * KEYD;    // [4096][2048]
static constexpr size_t OFF_ABCD  = OFF_VC    + (size_t)NTOK * VALD;    // [NTOK*HH][4] = alpha,beta,c,d
static constexpr size_t OFF_OPRE  = OFF_ABCD  + (size_t)NTOK * HH * 4;  // [4096][2048]
static constexpr size_t OFF_YN    = OFF_OPRE  + (size_t)NTOK * VALD;    // [4096][2048] tf32-rounded
static constexpr size_t ARENA_F   = OFF_YN    + (size_t)NTOK * VALD;

__device__ float g_arena[ARENA_F];

// ---------------------------------------------------------------------------
// TF32 helpers
// ---------------------------------------------------------------------------
__device__ __forceinline__ uint32_t f2tf32(float x) {
    uint32_t r;
    asm("cvt.rna.tf32.f32 %0, %1;" : "=r"(r) : "f"(x));
    return r;
}
__device__ __forceinline__ float tf32round(float x) {
    return __uint_as_float(f2tf32(x));
}

__device__ __forceinline__ void mma_tf32(float* c, const uint32_t* a, const uint32_t* b) {
    asm volatile(
        "mma.sync.aligned.m16n8k8.row.col.f32.tf32.tf32.f32 "
        "{%0,%1,%2,%3}, {%4,%5,%6,%7}, {%8,%9}, {%0,%1,%2,%3};"
        : "+f"(c[0]), "+f"(c[1]), "+f"(c[2]), "+f"(c[3])
        : "r"(a[0]), "r"(a[1]), "r"(a[2]), "r"(a[3]), "r"(b[0]), "r"(b[1]));
}

__device__ __forceinline__ void cp16(uint32_t smem_dst, const void* gsrc) {
    asm volatile("cp.async.cg.shared.global [%0], [%1], 16;" :: "r"(smem_dst), "l"(gsrc));
}

// ---------------------------------------------------------------------------
// Fast SiLU via single-instruction tanh.approx (sm_75+):
//   silu(x) = x * sigmoid(x) = 0.5*x*tanh(0.5*x) + 0.5*x
// ---------------------------------------------------------------------------
__device__ __forceinline__ float tanh_ap(float x) {
    float r;
    asm("tanh.approx.f32 %0, %1;" : "=f"(r) : "f"(x));
    return r;
}
__device__ __forceinline__ float silu_fast(float x) {
    float hx = 0.5f * x;
    return fmaf(hx, tanh_ap(hx), hx);
}

// ---------------------------------------------------------------------------
// Packed f32x2 helpers (Blackwell; PTX-only path)
// ---------------------------------------------------------------------------
__device__ __forceinline__ unsigned long long pk2(float lo, float hi) {
    unsigned long long r;
    asm("mov.b64 %0, {%1, %2};" : "=l"(r) : "f"(lo), "f"(hi));
    return r;
}
__device__ __forceinline__ void upk2(float& lo, float& hi, unsigned long long x) {
    asm("mov.b64 {%0, %1}, %2;" : "=f"(lo), "=f"(hi) : "l"(x));
}
__device__ __forceinline__ unsigned long long fma2_(unsigned long long a,
                                                    unsigned long long b,
                                                    unsigned long long c) {
    unsigned long long d;
    asm("fma.rn.f32x2 %0, %1, %2, %3;" : "=l"(d) : "l"(a), "l"(b), "l"(c));
    return d;
}
__device__ __forceinline__ unsigned long long mul2_(unsigned long long a,
                                                    unsigned long long b) {
    unsigned long long d;
    asm("mul.rn.f32x2 %0, %1, %2;" : "=l"(d) : "l"(a), "l"(b));
    return d;
}

// ---------------------------------------------------------------------------
// TF32 tensor-core GEMM, BM=128 x BN=64 CTA tile, 128 threads (4 warps 2x2),
// warp tile 64x32 (same per-warp workload as the proven 256-thread config ->
// regs ~96-127, so 4 CTAs/SM by regfile; smem 29.7KB). Double-buffered
// cp.async. M mult of 128, N mult of 64, K mult of 16.
// ---------------------------------------------------------------------------
#define GA_STRIDE 20
#define GB2_STRIDE 72

__global__ void __launch_bounds__(128) tf32gemm_kernel(
    const float* __restrict__ A, const float* __restrict__ B,
    float* __restrict__ C, int M, int N, int K)
{
    __shared__ float As[2][128 * GA_STRIDE];
    __shared__ float Bs[2][16 * GB2_STRIDE];

    const int tid  = threadIdx.x;
    const int bm   = blockIdx.y, bn = blockIdx.x;
    const int warp = tid >> 5, lane = tid & 31;
    const int wm   = (warp >> 1) * 64;       // 2x2 warp grid
    const int wn   = (warp & 1) * 32;
    const int gid  = lane >> 2;
    const int tg   = lane & 3;

    const float* Ag = A + (size_t)(bm * 128) * K;
    const float* Bg = B + (size_t)bn * 64;

    uint32_t as_base = (uint32_t)__cvta_generic_to_shared(&As[0][0]);
    uint32_t bs_base = (uint32_t)__cvta_generic_to_shared(&Bs[0][0]);
    const uint32_t as_buf = 128 * GA_STRIDE * 4;
    const uint32_t bs_buf = 16 * GB2_STRIDE * 4;

    float acc[4][4][4];
#pragma unroll
    for (int i = 0; i < 4; i++)
#pragma unroll
        for (int j = 0; j < 4; j++)
#pragma unroll
            for (int r = 0; r < 4; r++) acc[i][j][r] = 0.f;

    const int niter = K >> 4;

    // A tile 128x16: thread tid loads row tid, 4 cp16 at cols f*4.
    // B tile 16x64: 256 cp16; thread handles idx = tid + 128*f (f=0,1):
    //   row = idx>>4 (0..15), col = (idx&15)*4 (0..60).
#define ISSUE_TILE(bufsel, k0)                                                 \
    {                                                                          \
        uint32_t ao = as_base + (uint32_t)(bufsel) * as_buf;                   \
        uint32_t bo = bs_base + (uint32_t)(bufsel) * bs_buf;                   \
        _Pragma("unroll")                                                      \
        for (int f = 0; f < 4; f++) {                                          \
            cp16(ao + (uint32_t)((tid * GA_STRIDE + f * 4) << 2),              \
                 Ag + (size_t)tid * K + (k0) + f * 4);                         \
        }                                                                      \
        _Pragma("unroll")                                                      \
        for (int f = 0; f < 2; f++) {                                          \
            int idx = tid + 128 * f;                                           \
            int row = idx >> 4, col = (idx & 15) * 4;                          \
            cp16(bo + (uint32_t)((row * GB2_STRIDE + col) << 2),               \
                 Bg + (size_t)((k0) + row) * N + col);                         \
        }                                                                      \
        asm volatile("cp.async.commit_group;");                                \
    }

    ISSUE_TILE(0, 0);

    for (int it = 0; it < niter; it++) {
        const int p = it & 1;

        if (it + 1 < niter) {
            ISSUE_TILE(p ^ 1, (it + 1) << 4);
            asm volatile("cp.async.wait_group 1;");
        } else {
            asm volatile("cp.async.wait_group 0;");
        }
        __syncthreads();

        const float* Ap = As[p];
        const float* Bp = Bs[p];

#pragma unroll
        for (int ks = 0; ks < 2; ks++) {
            uint32_t af[4][4];
#pragma unroll
            for (int mt = 0; mt < 4; mt++) {
                int r = wm + mt * 16 + gid;
                int c = ks * 8 + tg;
                af[mt][0] = __float_as_uint(Ap[r * GA_STRIDE + c]);
                af[mt][1] = __float_as_uint(Ap[(r + 8) * GA_STRIDE + c]);
                af[mt][2] = __float_as_uint(Ap[r * GA_STRIDE + c + 4]);
                af[mt][3] = __float_as_uint(Ap[(r + 8) * GA_STRIDE + c + 4]);
            }
            uint32_t bf[4][2];
#pragma unroll
            for (int nt = 0; nt < 4; nt++) {
                int n = wn + nt * 8 + gid;
                bf[nt][0] = __float_as_uint(Bp[(ks * 8 + tg) * GB2_STRIDE + n]);
                bf[nt][1] = __float_as_uint(Bp[(ks * 8 + 4 + tg) * GB2_STRIDE + n]);
            }
#pragma unroll
            for (int mt = 0; mt < 4; mt++)
#pragma unroll
                for (int nt = 0; nt < 4; nt++)
                    mma_tf32(acc[mt][nt], af[mt], bf[nt]);
        }
        __syncthreads();
    }
#undef ISSUE_TILE

#pragma unroll
    for (int mt = 0; mt < 4; mt++) {
        int r0 = bm * 128 + wm + mt * 16 + gid;
#pragma unroll
        for (int nt = 0; nt < 4; nt++) {
            int c0 = bn * 64 + wn + nt * 8 + tg * 2;
            *(float2*)(C + (size_t)r0 * N + c0)       = make_float2(acc[mt][nt][0], acc[mt][nt][1]);
            *(float2*)(C + (size_t)(r0 + 8) * N + c0) = make_float2(acc[mt][nt][2], acc[mt][nt][3]);
        }
    }
}

// ---------------------------------------------------------------------------
// Prep kernel (launch 1)
// ---------------------------------------------------------------------------
#define NB_WPACK 24576
#define NB_AB    64
#define NB_XR    16384
#define NB_WOR   8192

__global__ void __launch_bounds__(256) prep_kernel(
    const float* __restrict__ Wq, const float* __restrict__ Wk,
    const float* __restrict__ Wv, const float* __restrict__ Wg,
    const float* __restrict__ Wa, const float* __restrict__ Wb,
    const float* __restrict__ Wo, const float* __restrict__ x,
    float* __restrict__ wpack, float* __restrict__ wabt,
    float* __restrict__ xr, float* __restrict__ wor)
{
    int bid = blockIdx.x;
    if (bid < NB_WPACK) {
        int idx = bid * 256 + threadIdx.x;
        int col = idx % PS, k = idx / PS;
        float v;
        if (col < 1024)      v = Wq[k * 1024 + col];
        else if (col < 2048) v = Wk[k * 1024 + col - 1024];
        else if (col < 4096) v = Wv[k * 2048 + col - 2048];
        else                 v = Wg[k * 2048 + col - 4096];
        wpack[idx] = tf32round(v);
    } else if (bid < NB_WPACK + NB_AB) {
        int idx = (bid - NB_WPACK) * 256 + threadIdx.x;
        int k = idx & 1023, h = (idx >> 10) & 7, a = idx >> 13;
        wabt[idx] = a ? Wb[k * 8 + h] : Wa[k * 8 + h];
    } else if (bid < NB_WPACK + NB_AB + NB_XR) {
        int idx = (bid - NB_WPACK - NB_AB) * 256 + threadIdx.x;
        xr[idx] = tf32round(x[idx]);
    } else {
        int idx = (bid - NB_WPACK - NB_AB - NB_XR) * 256 + threadIdx.x;
        wor[idx] = tf32round(Wo[idx]);
    }
}

// ---------------------------------------------------------------------------
// Fused elementwise kernel (launch 3): ab + conv_q + conv_k + conv_v.
// ---------------------------------------------------------------------------
#define FB_AB   4096
#define FB_CQ   4096
#define FB_CK   4096
#define FB_CV   32768

__device__ __forceinline__ void do_conv_l2(
    const float* __restrict__ in, const float* __restrict__ w,
    float* __restrict__ out, int local_blk)
{
    int gw   = ((local_blk * 256) + (int)threadIdx.x) >> 5;
    int lane = threadIdx.x & 31;
    int h    = gw % HH;
    int bt   = gw / HH;
    int t    = bt % TSEQ;
    int b    = bt / TSEQ;

    int cbase = h * KDIM + lane * 4;

    float acc[4] = {0.f, 0.f, 0.f, 0.f};
    float wt[4][KS];
#pragma unroll
    for (int c = 0; c < 4; c++)
#pragma unroll
        for (int j = 0; j < KS; j++)
            wt[c][j] = w[(cbase + c) * KS + j];

#pragma unroll
    for (int j = 0; j < KS; j++) {
        int tt = t + j - (KS - 1);
        if (tt >= 0) {
            float4 xv = *(const float4*)(in + ((size_t)(b * TSEQ + tt)) * PS + cbase);
#pragma unroll
            for (int c = 0; c < 4; c++)
                acc[c] = fmaf(wt[c][j], (&xv.x)[c], acc[c]);
        }
    }

    float ss = 0.f;
#pragma unroll
    for (int c = 0; c < 4; c++) {
        acc[c] = silu_fast(acc[c]);
        ss = fmaf(acc[c], acc[c], ss);
    }
#pragma unroll
    for (int off = 16; off > 0; off >>= 1)
        ss += __shfl_xor_sync(0xffffffffu, ss, off);
    float s = 1.f / fmaxf(sqrtf(ss), 1e-6f);

    float4 o;
#pragma unroll
    for (int c = 0; c < 4; c++) (&o.x)[c] = acc[c] * s;
    *(float4*)(out + (size_t)bt * KEYD + cbase) = o;
}

__global__ void __launch_bounds__(256) fused_pre_kernel(
    const float* __restrict__ x, const float* __restrict__ proj,
    const float* __restrict__ wabt,
    const float* __restrict__ A_log, const float* __restrict__ dt_bias,
    const float* __restrict__ conv_q, const float* __restrict__ conv_k,
    const float* __restrict__ conv_v,
    float* __restrict__ abcd,
    float* __restrict__ qc, float* __restrict__ kc, float* __restrict__ vc)
{
    __shared__ float xs[DD];
    int bid = blockIdx.x;

    if (bid < FB_AB) {
        int t = bid;
        for (int i = threadIdx.x; i < DD; i += 256)
            xs[i] = x[(size_t)t * DD + i];
        __syncthreads();

        int warp = threadIdx.x >> 5;
        int lane = threadIdx.x & 31;
        const float* wa = wabt + warp * 1024;
        const float* wb = wabt + 8192 + warp * 1024;

        float sa = 0.f, sb = 0.f;
#pragma unroll 4
        for (int kk = lane; kk < DD; kk += 32) {
            float xv = xs[kk];
            sa = fmaf(xv, wa[kk], sa);
            sb = fmaf(xv, wb[kk], sb);
        }
#pragma unroll
        for (int off = 16; off > 0; off >>= 1) {
            sa += __shfl_xor_sync(0xffffffffu, sa, off);
            sb += __shfl_xor_sync(0xffffffffu, sb, off);
        }
        if (lane == 0) {
            float z  = sa + dt_bias[warp];
            float sp = (z > 20.f) ? z : log1pf(expf(z));
            float alpha = expf(-expf(A_log[warp]) * sp);
            float beta  = 1.f + tanh_ap(0.5f * sb);   // 2*sigmoid(sb)
            *(float2*)(abcd + (size_t)(t * HH + warp) * 4) = make_float2(alpha, beta);
        }
    } else if (bid < FB_AB + FB_CQ) {
        do_conv_l2(proj + QO, conv_q, qc, bid - FB_AB);
    } else if (bid < FB_AB + FB_CQ + FB_CK) {
        do_conv_l2(proj + KO, conv_k, kc, bid - FB_AB - FB_CQ);
    } else {
        int idx = (bid - FB_AB - FB_CQ - FB_CK) * 256 + threadIdx.x;
        int c  = idx % VALD;
        int bt = idx / VALD;
        int t  = bt % TSEQ;
        int b  = bt / TSEQ;

        float acc = 0.f;
#pragma unroll
        for (int j = 0; j < KS; j++) {
            int tt = t + j - (KS - 1);
            if (tt >= 0)
                acc = fmaf(conv_v[c * KS + j],
                           proj[VO + ((size_t)(b * TSEQ + tt)) * PS + c], acc);
        }
        vc[idx] = silu_fast(acc);
    }
}

// ---------------------------------------------------------------------------
// ckd kernel (launch 4): c_t = k_t.k_{t+1} (0 at seq end), d_t = k_t.q_t
// ---------------------------------------------------------------------------
__global__ void __launch_bounds__(256) ckd_kernel(
    const float* __restrict__ qc, const float* __restrict__ kc,
    float* __restrict__ abcd)
{
    int gw   = (blockIdx.x * 256 + threadIdx.x) >> 5;   // bt*HH + h
    int lane = threadIdx.x & 31;
    int h    = gw & 7;
    int bt   = gw >> 3;
    int t    = bt & (TSEQ - 1);

    const float* kp = kc + (size_t)bt * KEYD + h * KDIM + lane * 4;
    const float* qp = qc + (size_t)bt * KEYD + h * KDIM + lane * 4;
    float4 kt = *(const float4*)kp;
    float4 qt = *(const float4*)qp;
    float4 kn = make_float4(0.f, 0.f, 0.f, 0.f);
    if (t < TSEQ - 1) kn = *(const float4*)(kp + KEYD);

    float c = kt.x * kn.x + kt.y * kn.y + kt.z * kn.z + kt.w * kn.w;
    float d = kt.x * qt.x + kt.y * qt.y + kt.z * qt.z + kt.w * qt.w;
#pragma unroll
    for (int off = 16; off > 0; off >>= 1) {
        c += __shfl_xor_sync(0xffffffffu, c, off);
        d += __shfl_xor_sync(0xffffffffu, d, off);
    }
    if (lane == 0)
        *(float2*)(abcd + (size_t)gw * 4 + 2) = make_float2(c, d);
}

// ---------------------------------------------------------------------------
// Recurrent delta-rule scan (launch 5): lookahead-1 algebra + packed f32x2
// state + cp.async double-buffered smem staging (CH=16 timesteps/chunk).
// ---------------------------------------------------------------------------
#define CH     16
#define NCH    (TSEQ / CH)     // 128
#define ROW_W  160             // words per padded k/q row (8 * 20)
#define ROW_B  (ROW_W * 4)     // 640 bytes

__global__ void __launch_bounds__(256) scan_kernel(
    const float* __restrict__ q, const float* __restrict__ k,
    const float* __restrict__ v, const float* __restrict__ abcd,
    float* __restrict__ o)
{
    __shared__ __align__(16) float sk [2][(CH + 1) * ROW_W];
    __shared__ __align__(16) float sq [2][CH * ROW_W];
    __shared__ __align__(16) float sv [2][CH * 32];
    __shared__ __align__(16) float ssc[2][CH * 4];

    int bid  = blockIdx.x;
    int vblk = bid & 7;
    int h    = (bid >> 3) & 7;
    int b    = bid >> 6;

    int tid   = threadIdx.x;
    int warp  = tid >> 5;
    int lane  = tid & 31;
    int rowid = lane & 3;
    int ksub  = lane >> 2;
    int vloc  = warp * 4 + rowid;           // 0..31

    const float* kg = k + (size_t)(b * TSEQ) * KEYD + h * KDIM;
    const float* qg = q + (size_t)(b * TSEQ) * KEYD + h * KDIM;
    const float* vg = v + (size_t)(b * TSEQ) * VALD + h * VDIM + vblk * 32;
    const float* sg = abcd + (size_t)(b * TSEQ) * (HH * 4) + h * 4;
    float*       og = o + (size_t)(b * TSEQ) * VALD + h * VDIM + vblk * 32 + vloc;

    uint32_t skb  = (uint32_t)__cvta_generic_to_shared(&sk[0][0]);
    uint32_t sqb  = (uint32_t)__cvta_generic_to_shared(&sq[0][0]);
    uint32_t svb  = (uint32_t)__cvta_generic_to_shared(&sv[0][0]);
    uint32_t sscb = (uint32_t)__cvta_generic_to_shared(&ssc[0][0]);
    const uint32_t SKBUF  = (CH + 1) * ROW_B;
    const uint32_t SQBUF  = CH * ROW_B;
    const uint32_t SVBUF  = CH * 32 * 4;
    const uint32_t SSCBUF = CH * 16;

#define ISSUE_CHUNK(p, base)                                                   \
    {                                                                          \
        uint32_t kb = skb + (uint32_t)(p) * SKBUF;                             \
        _Pragma("unroll")                                                      \
        for (int pass = 0; pass < 3; pass++) {                                 \
            int f = tid + pass * 256;                                          \
            if (f < (CH + 1) * 32) {                                           \
                int row = f >> 5, m = f & 31;                                  \
                int t = (base) + row; t = t < TSEQ ? t : TSEQ - 1;             \
                cp16(kb + (uint32_t)(row * ROW_B + (m >> 2) * 80 + (m & 3) * 16), \
                     kg + (size_t)t * KEYD + m * 4);                           \
            }                                                                  \
        }                                                                      \
        uint32_t qb = sqb + (uint32_t)(p) * SQBUF;                             \
        _Pragma("unroll")                                                      \
        for (int pass = 0; pass < 2; pass++) {                                 \
            int f = tid + pass * 256;                                          \
            int row = f >> 5, m = f & 31;                                      \
            cp16(qb + (uint32_t)(row * ROW_B + (m >> 2) * 80 + (m & 3) * 16),  \
                 qg + (size_t)((base) + row) * KEYD + m * 4);                  \
        }                                                                      \
        if (tid < 128) {                                                       \
            int row = tid >> 3, j = tid & 7;                                   \
            cp16(svb + (uint32_t)(p) * SVBUF + (uint32_t)((row * 32 + j * 4) * 4), \
                 vg + (size_t)((base) + row) * VALD + j * 4);                  \
        }                                                                      \
        if (tid < CH) {                                                        \
            cp16(sscb + (uint32_t)(p) * SSCBUF + (uint32_t)(tid * 16),         \
                 sg + (size_t)((base) + tid) * (HH * 4));                      \
        }                                                                      \
        asm volatile("cp.async.commit_group;");                                \
    }

    unsigned long long S2[8];
#pragma unroll
    for (int i = 0; i < 8; i++) S2[i] = 0ull;
    float u = 0.f, pa = 0.f, pcoef = 0.f, pcc = 0.f;

    ISSUE_CHUNK(0, 0);

    for (int c = 0; c < NCH; c++) {
        int p = c & 1;
        if (c + 1 < NCH) {
            ISSUE_CHUNK(p ^ 1, (c + 1) * CH);
            asm volatile("cp.async.wait_group 1;");
        } else {
            asm volatile("cp.async.wait_group 0;");
        }
        __syncthreads();

        const char* skp = (const char*)&sk[p][0];
        const char* sqp = (const char*)&sq[p][0];
        const float* svp = &sv[p][0];
        const float* sscp = &ssc[p][0];
        int base = c * CH;

#pragma unroll 4
        for (int tl = 0; tl < CH; tl++) {
            float4 sc = *(const float4*)(sscp + tl * 4);
            float aa = sc.x, bv = sc.y, cc = sc.z, dd = sc.w;
            float vv = svp[tl * 32 + vloc];

            float r    = fmaf(pa, u, pcoef * pcc);
            float coef = fmaf(-(aa * bv), r, bv * vv);

            const char* krow = skp + tl * ROW_B + ksub * 80;
            const char* qrow = sqp + tl * ROW_B + ksub * 80;

            unsigned long long ua = 0ull, wa = 0ull;
#pragma unroll
            for (int i = 0; i < 8; i++) {
                unsigned long long kn = *(const unsigned long long*)(krow + ROW_B + i * 8);
                unsigned long long qq = *(const unsigned long long*)(qrow + i * 8);
                ua = fma2_(S2[i], kn, ua);
                wa = fma2_(S2[i], qq, wa);
            }
            float ul, uh, wl, wh;
            upk2(ul, uh, ua);
            upk2(wl, wh, wa);
            float un = ul + uh, wn = wl + wh;
            un += __shfl_xor_sync(0xffffffffu, un, 4);
            un += __shfl_xor_sync(0xffffffffu, un, 8);
            un += __shfl_xor_sync(0xffffffffu, un, 16);
            wn += __shfl_xor_sync(0xffffffffu, wn, 4);
            wn += __shfl_xor_sync(0xffffffffu, wn, 8);
            wn += __shfl_xor_sync(0xffffffffu, wn, 16);

            unsigned long long aa2 = pk2(aa, aa);
            unsigned long long cf2 = pk2(coef, coef);
#pragma unroll
            for (int i = 0; i < 8; i++) {
                unsigned long long kt = *(const unsigned long long*)(krow + i * 8);
                S2[i] = fma2_(kt, cf2, mul2_(aa2, S2[i]));
            }

            float ov = fmaf(coef, dd, aa * wn);
            if (ksub == 0) og[(size_t)(base + tl) * VALD] = ov;

            u = un; pa = aa; pcoef = coef; pcc = cc;
        }
        __syncthreads();
    }
#undef ISSUE_CHUNK
}

// ---------------------------------------------------------------------------
// RMS norm + weight + SiLU(gate), tf32-rounded output. One warp per (bt,h).
// ---------------------------------------------------------------------------
__global__ void __launch_bounds__(256) normgate_kernel(
    const float* __restrict__ o, const float* __restrict__ proj,
    const float* __restrict__ w, float* __restrict__ y)
{
    int gw   = (blockIdx.x * 256 + threadIdx.x) >> 5;   // bt*H + h
    int lane = threadIdx.x & 31;
    int bt   = gw >> 3, h = gw & 7;

    const float* op = o + (size_t)gw * VDIM + lane * 8;
    const float* gp = proj + GO + (size_t)bt * PS + h * VDIM + lane * 8;
    float*       yp = y + (size_t)gw * VDIM + lane * 8;

    float vals[8];
    *(float4*)(vals)     = *(const float4*)(op);
    *(float4*)(vals + 4) = *(const float4*)(op + 4);

    float ss = 0.f;
#pragma unroll
    for (int i = 0; i < 8; i++) ss = fmaf(vals[i], vals[i], ss);
#pragma unroll
    for (int off = 16; off > 0; off >>= 1)
        ss += __shfl_xor_sync(0xffffffffu, ss, off);
    float rms = rsqrtf(ss * (1.f / VDIM) + 1e-5f);

    float gv[8];
    *(float4*)(gv)     = *(const float4*)(gp);
    *(float4*)(gv + 4) = *(const float4*)(gp + 4);

    float out[8];
#pragma unroll
    for (int i = 0; i < 8; i++) {
        float silu = silu_fast(gv[i]);
        out[i] = tf32round(vals[i] * rms * w[lane * 8 + i] * silu);
    }
    *(float4*)(yp)     = *(float4*)(out);
    *(float4*)(yp + 4) = *(float4*)(out + 4);
}

// ---------------------------------------------------------------------------
// Host launcher
// ---------------------------------------------------------------------------
extern "C" void kernel_launch(void* const* d_in, const int* in_sizes, int n_in,
                              void* d_out, int out_size)
{
    const float* x       = (const float*)d_in[0];
    const float* Wq      = (const float*)d_in[1];
    const float* Wk      = (const float*)d_in[2];
    const float* Wv      = (const float*)d_in[3];
    const float* Wa      = (const float*)d_in[4];
    const float* Wb      = (const float*)d_in[5];
    const float* Wg      = (const float*)d_in[6];
    const float* Wo      = (const float*)d_in[7];
    const float* A_log   = (const float*)d_in[8];
    const float* dt_bias = (const float*)d_in[9];
    const float* conv_q  = (const float*)d_in[10];
    const float* conv_k  = (const float*)d_in[11];
    const float* conv_v  = (const float*)d_in[12];
    const float* o_w     = (const float*)d_in[13];
    float* out = (float*)d_out;

    float* arena = nullptr;
    cudaGetSymbolAddress((void**)&arena, g_arena);

    float* wpack = arena + OFF_WPACK;
    float* xr    = arena + OFF_XR;
    float* wor   = arena + OFF_WOR;
    float* wabt  = arena + OFF_WABT;
    float* proj  = arena + OFF_PROJ;
    float* qc    = arena + OFF_QC;
    float* kc    = arena + OFF_KC;
    float* vc    = arena + OFF_VC;
    float* abcd  = arena + OFF_ABCD;
    float* opre  = arena + OFF_OPRE;
    float* yn    = arena + OFF_YN;

    dim3 blk(256);
    dim3 gblk(128);   // GEMM CTA: 128 threads, 128x64 tile

    // 1. pack + tf32-round all GEMM operands
    prep_kernel<<<NB_WPACK + NB_AB + NB_XR + NB_WOR, blk>>>(
        Wq, Wk, Wv, Wg, Wa, Wb, Wo, x, wpack, wabt, xr, wor);

    // 2. fused q|k|v|g projection (pre-rounded TF32)
    tf32gemm_kernel<<<dim3(PS / 64, NTOK / 128), gblk>>>(xr, wpack, proj, NTOK, PS, DD);

    // 3. fused alpha/beta + convs (tanh-approx SiLU)
    fused_pre_kernel<<<FB_AB + FB_CQ + FB_CK + FB_CV, blk>>>(
        x, proj, wabt, A_log, dt_bias, conv_q, conv_k, conv_v,
        abcd, qc, kc, vc);

    // 4. precompute c = k_t.k_{t+1}, d = k_t.q_t
    ckd_kernel<<<(NTOK * HH) / 8, blk>>>(qc, kc, abcd);

    // 5. recurrent scan (lookahead-1, packed f32x2, smem-staged)
    scan_kernel<<<BB * HH * (VDIM / 32), blk>>>(qc, kc, vc, abcd, opre);

    // 6. rms norm + gate (tanh-approx SiLU, tf32-rounded output)
    normgate_kernel<<<(NTOK * HH) / 8, blk>>>(opre, proj, o_w, yn);

    // 7. output projection (pre-rounded TF32)
    tf32gemm_kernel<<<dim3(DD / 64, NTOK / 128), gblk>>>(yn, wor, out, NTOK, DD, VALD);
}

// round 15
// speedup vs baseline: 1.2890x; 1.2890x over previous
#include <cuda_runtime.h>
#include <math.h>
#include <stdint.h>

// ---------------------------------------------------------------------------
// Problem constants
// ---------------------------------------------------------------------------
#define BB    2
#define TSEQ  2048
#define DD    1024
#define HH    8
#define KDIM  128
#define VDIM  256
#define KEYD  1024          // H*KDIM
#define VALD  2048          // H*VDIM
#define NTOK  (BB*TSEQ)     // 4096
#define KS    4
#define PS    6144          // packed projection row stride (q|k|v|g)
#define QO    0
#define KO    1024
#define VO    2048
#define GO    4096

// ---------------------------------------------------------------------------
// Scratch arena (device global — no allocation allowed)
// ---------------------------------------------------------------------------
static constexpr size_t OFF_WPACK = 0;                                  // [1024][6144] tf32-rounded
static constexpr size_t OFF_XR    = OFF_WPACK + (size_t)DD * PS;        // [4096][1024] tf32-rounded x
static constexpr size_t OFF_WOR   = OFF_XR    + (size_t)NTOK * DD;      // [2048][1024] tf32-rounded Wo
static constexpr size_t OFF_WABT  = OFF_WOR   + (size_t)VALD * DD;      // [2][8][1024]
static constexpr size_t OFF_PROJ  = OFF_WABT  + (size_t)2 * HH * DD;    // [4096][6144]
static constexpr size_t OFF_QC    = OFF_PROJ  + (size_t)NTOK * PS;      // [4096][1024]
static constexpr size_t OFF_KC    = OFF_QC    + (size_t)NTOK * KEYD;
static constexpr size_t OFF_VC    = OFF_KC    + (size_t)NTOK * KEYD;    // [4096][2048]
static constexpr size_t OFF_ABCD  = OFF_VC    + (size_t)NTOK * VALD;    // [NTOK*HH][4] = alpha,beta,c,d
static constexpr size_t OFF_OPRE  = OFF_ABCD  + (size_t)NTOK * HH * 4;  // [4096][2048]
static constexpr size_t OFF_YN    = OFF_OPRE  + (size_t)NTOK * VALD;    // [4096][2048] tf32-rounded
static constexpr size_t ARENA_F   = OFF_YN    + (size_t)NTOK * VALD;

__device__ float g_arena[ARENA_F];

// ---------------------------------------------------------------------------
// TF32 helpers
// ---------------------------------------------------------------------------
__device__ __forceinline__ uint32_t f2tf32(float x) {
    uint32_t r;
    asm("cvt.rna.tf32.f32 %0, %1;" : "=r"(r) : "f"(x));
    return r;
}
__device__ __forceinline__ float tf32round(float x) {
    return __uint_as_float(f2tf32(x));
}

__device__ __forceinline__ void mma_tf32(float* c, const uint32_t* a, const uint32_t* b) {
    asm volatile(
        "mma.sync.aligned.m16n8k8.row.col.f32.tf32.tf32.f32 "
        "{%0,%1,%2,%3}, {%4,%5,%6,%7}, {%8,%9}, {%0,%1,%2,%3};"
        : "+f"(c[0]), "+f"(c[1]), "+f"(c[2]), "+f"(c[3])
        : "r"(a[0]), "r"(a[1]), "r"(a[2]), "r"(a[3]), "r"(b[0]), "r"(b[1]));
}

__device__ __forceinline__ void cp16(uint32_t smem_dst, const void* gsrc) {
    asm volatile("cp.async.cg.shared.global [%0], [%1], 16;" :: "r"(smem_dst), "l"(gsrc));
}

// ---------------------------------------------------------------------------
// Fast SiLU via single-instruction tanh.approx (sm_75+):
//   silu(x) = x * sigmoid(x) = 0.5*x*tanh(0.5*x) + 0.5*x
// ---------------------------------------------------------------------------
__device__ __forceinline__ float tanh_ap(float x) {
    float r;
    asm("tanh.approx.f32 %0, %1;" : "=f"(r) : "f"(x));
    return r;
}
__device__ __forceinline__ float silu_fast(float x) {
    float hx = 0.5f * x;
    return fmaf(hx, tanh_ap(hx), hx);
}

// ---------------------------------------------------------------------------
// Packed f32x2 helpers (Blackwell; PTX-only path)
// ---------------------------------------------------------------------------
__device__ __forceinline__ unsigned long long pk2(float lo, float hi) {
    unsigned long long r;
    asm("mov.b64 %0, {%1, %2};" : "=l"(r) : "f"(lo), "f"(hi));
    return r;
}
__device__ __forceinline__ void upk2(float& lo, float& hi, unsigned long long x) {
    asm("mov.b64 {%0, %1}, %2;" : "=f"(lo), "=f"(hi) : "l"(x));
}
__device__ __forceinline__ unsigned long long fma2_(unsigned long long a,
                                                    unsigned long long b,
                                                    unsigned long long c) {
    unsigned long long d;
    asm("fma.rn.f32x2 %0, %1, %2, %3;" : "=l"(d) : "l"(a), "l"(b), "l"(c));
    return d;
}
__device__ __forceinline__ unsigned long long mul2_(unsigned long long a,
                                                    unsigned long long b) {
    unsigned long long d;
    asm("mul.rn.f32x2 %0, %1, %2;" : "=l"(d) : "l"(a), "l"(b));
    return d;
}

// ---------------------------------------------------------------------------
// TF32 tensor-core GEMM on PRE-ROUNDED operands (R11/R13-measured config:
// 256 threads, 8 warps 2x4, warp tile 64x32, double-buffered cp.async).
// ---------------------------------------------------------------------------
#define GA_STRIDE 20
#define GB_STRIDE 136

__global__ void __launch_bounds__(256) tf32gemm_kernel(
    const float* __restrict__ A, const float* __restrict__ B,
    float* __restrict__ C, int M, int N, int K)
{
    __shared__ float As[2][128 * GA_STRIDE];
    __shared__ float Bs[2][16 * GB_STRIDE];

    const int tid  = threadIdx.x;
    const int bm   = blockIdx.y, bn = blockIdx.x;
    const int warp = tid >> 5, lane = tid & 31;
    const int wm   = (warp >> 2) * 64;
    const int wn   = (warp & 3) * 32;
    const int gid  = lane >> 2;
    const int tg   = lane & 3;

    const int a_r0 = tid >> 2;
    const int a_c  = (tid & 3) * 4;
    const int b_r0 = tid >> 5;
    const int b_c  = (tid & 31) * 4;

    const float* Ag = A + (size_t)(bm * 128) * K;
    const float* Bg = B + (size_t)bn * 128;

    uint32_t as_base = (uint32_t)__cvta_generic_to_shared(&As[0][0]);
    uint32_t bs_base = (uint32_t)__cvta_generic_to_shared(&Bs[0][0]);
    const uint32_t as_buf = 128 * GA_STRIDE * 4;
    const uint32_t bs_buf = 16 * GB_STRIDE * 4;

    float acc[4][4][4];
#pragma unroll
    for (int i = 0; i < 4; i++)
#pragma unroll
        for (int j = 0; j < 4; j++)
#pragma unroll
            for (int r = 0; r < 4; r++) acc[i][j][r] = 0.f;

    const int niter = K >> 4;

    {
#pragma unroll
        for (int f = 0; f < 2; f++) {
            int row = f * 64 + a_r0;
            cp16(as_base + (uint32_t)((row * GA_STRIDE + a_c) << 2),
                 Ag + (size_t)row * K + a_c);
        }
#pragma unroll
        for (int f = 0; f < 2; f++) {
            int row = f * 8 + b_r0;
            cp16(bs_base + (uint32_t)((row * GB_STRIDE + b_c) << 2),
                 Bg + (size_t)row * N + b_c);
        }
        asm volatile("cp.async.commit_group;");
    }

    for (int it = 0; it < niter; it++) {
        const int p = it & 1;

        if (it + 1 < niter) {
            const int k0 = (it + 1) << 4;
            const uint32_t ao = as_base + (p ^ 1) * as_buf;
            const uint32_t bo = bs_base + (p ^ 1) * bs_buf;
#pragma unroll
            for (int f = 0; f < 2; f++) {
                int row = f * 64 + a_r0;
                cp16(ao + (uint32_t)((row * GA_STRIDE + a_c) << 2),
                     Ag + (size_t)row * K + k0 + a_c);
            }
#pragma unroll
            for (int f = 0; f < 2; f++) {
                int row = f * 8 + b_r0;
                cp16(bo + (uint32_t)((row * GB_STRIDE + b_c) << 2),
                     Bg + (size_t)(k0 + row) * N + b_c);
            }
            asm volatile("cp.async.commit_group;");
            asm volatile("cp.async.wait_group 1;");
        } else {
            asm volatile("cp.async.wait_group 0;");
        }
        __syncthreads();

        const float* Ap = As[p];
        const float* Bp = Bs[p];

#pragma unroll
        for (int ks = 0; ks < 2; ks++) {
            uint32_t af[4][4];
#pragma unroll
            for (int mt = 0; mt < 4; mt++) {
                int r = wm + mt * 16 + gid;
                int c = ks * 8 + tg;
                af[mt][0] = __float_as_uint(Ap[r * GA_STRIDE + c]);
                af[mt][1] = __float_as_uint(Ap[(r + 8) * GA_STRIDE + c]);
                af[mt][2] = __float_as_uint(Ap[r * GA_STRIDE + c + 4]);
                af[mt][3] = __float_as_uint(Ap[(r + 8) * GA_STRIDE + c + 4]);
            }
            uint32_t bf[4][2];
#pragma unroll
            for (int nt = 0; nt < 4; nt++) {
                int n = wn + nt * 8 + gid;
                bf[nt][0] = __float_as_uint(Bp[(ks * 8 + tg) * GB_STRIDE + n]);
                bf[nt][1] = __float_as_uint(Bp[(ks * 8 + 4 + tg) * GB_STRIDE + n]);
            }
#pragma unroll
            for (int mt = 0; mt < 4; mt++)
#pragma unroll
                for (int nt = 0; nt < 4; nt++)
                    mma_tf32(acc[mt][nt], af[mt], bf[nt]);
        }
        __syncthreads();
    }

#pragma unroll
    for (int mt = 0; mt < 4; mt++) {
        int r0 = bm * 128 + wm + mt * 16 + gid;
#pragma unroll
        for (int nt = 0; nt < 4; nt++) {
            int c0 = bn * 128 + wn + nt * 8 + tg * 2;
            *(float2*)(C + (size_t)r0 * N + c0)       = make_float2(acc[mt][nt][0], acc[mt][nt][1]);
            *(float2*)(C + (size_t)(r0 + 8) * N + c0) = make_float2(acc[mt][nt][2], acc[mt][nt][3]);
        }
    }
}

// ---------------------------------------------------------------------------
// Prep kernel (launch 1)
// ---------------------------------------------------------------------------
#define NB_WPACK 24576
#define NB_AB    64
#define NB_XR    16384
#define NB_WOR   8192

__global__ void __launch_bounds__(256) prep_kernel(
    const float* __restrict__ Wq, const float* __restrict__ Wk,
    const float* __restrict__ Wv, const float* __restrict__ Wg,
    const float* __restrict__ Wa, const float* __restrict__ Wb,
    const float* __restrict__ Wo, const float* __restrict__ x,
    float* __restrict__ wpack, float* __restrict__ wabt,
    float* __restrict__ xr, float* __restrict__ wor)
{
    int bid = blockIdx.x;
    if (bid < NB_WPACK) {
        int idx = bid * 256 + threadIdx.x;
        int col = idx % PS, k = idx / PS;
        float v;
        if (col < 1024)      v = Wq[k * 1024 + col];
        else if (col < 2048) v = Wk[k * 1024 + col - 1024];
        else if (col < 4096) v = Wv[k * 2048 + col - 2048];
        else                 v = Wg[k * 2048 + col - 4096];
        wpack[idx] = tf32round(v);
    } else if (bid < NB_WPACK + NB_AB) {
        int idx = (bid - NB_WPACK) * 256 + threadIdx.x;
        int k = idx & 1023, h = (idx >> 10) & 7, a = idx >> 13;
        wabt[idx] = a ? Wb[k * 8 + h] : Wa[k * 8 + h];
    } else if (bid < NB_WPACK + NB_AB + NB_XR) {
        int idx = (bid - NB_WPACK - NB_AB) * 256 + threadIdx.x;
        xr[idx] = tf32round(x[idx]);
    } else {
        int idx = (bid - NB_WPACK - NB_AB - NB_XR) * 256 + threadIdx.x;
        wor[idx] = tf32round(Wo[idx]);
    }
}

// ---------------------------------------------------------------------------
// Fused elementwise kernel (launch 3): ab + conv_q + conv_k + conv_v.
// conv_v: each thread computes 4 consecutive timesteps of one channel
// (7 loads -> 4 outputs; tap FMA order identical to before).
// ---------------------------------------------------------------------------
#define FB_AB   4096
#define FB_CQ   4096
#define FB_CK   4096
#define FB_CV   8192        // NTOK/4 * VALD / 256

__device__ __forceinline__ void do_conv_l2(
    const float* __restrict__ in, const float* __restrict__ w,
    float* __restrict__ out, int local_blk)
{
    int gw   = ((local_blk * 256) + (int)threadIdx.x) >> 5;
    int lane = threadIdx.x & 31;
    int h    = gw % HH;
    int bt   = gw / HH;
    int t    = bt % TSEQ;
    int b    = bt / TSEQ;

    int cbase = h * KDIM + lane * 4;

    float acc[4] = {0.f, 0.f, 0.f, 0.f};
    float wt[4][KS];
#pragma unroll
    for (int c = 0; c < 4; c++)
#pragma unroll
        for (int j = 0; j < KS; j++)
            wt[c][j] = w[(cbase + c) * KS + j];

#pragma unroll
    for (int j = 0; j < KS; j++) {
        int tt = t + j - (KS - 1);
        if (tt >= 0) {
            float4 xv = *(const float4*)(in + ((size_t)(b * TSEQ + tt)) * PS + cbase);
#pragma unroll
            for (int c = 0; c < 4; c++)
                acc[c] = fmaf(wt[c][j], (&xv.x)[c], acc[c]);
        }
    }

    float ss = 0.f;
#pragma unroll
    for (int c = 0; c < 4; c++) {
        acc[c] = silu_fast(acc[c]);
        ss = fmaf(acc[c], acc[c], ss);
    }
#pragma unroll
    for (int off = 16; off > 0; off >>= 1)
        ss += __shfl_xor_sync(0xffffffffu, ss, off);
    float s = 1.f / fmaxf(sqrtf(ss), 1e-6f);

    float4 o;
#pragma unroll
    for (int c = 0; c < 4; c++) (&o.x)[c] = acc[c] * s;
    *(float4*)(out + (size_t)bt * KEYD + cbase) = o;
}

__global__ void __launch_bounds__(256) fused_pre_kernel(
    const float* __restrict__ x, const float* __restrict__ proj,
    const float* __restrict__ wabt,
    const float* __restrict__ A_log, const float* __restrict__ dt_bias,
    const float* __restrict__ conv_q, const float* __restrict__ conv_k,
    const float* __restrict__ conv_v,
    float* __restrict__ abcd,
    float* __restrict__ qc, float* __restrict__ kc, float* __restrict__ vc)
{
    __shared__ float xs[DD];
    int bid = blockIdx.x;

    if (bid < FB_AB) {
        int t = bid;
        for (int i = threadIdx.x; i < DD; i += 256)
            xs[i] = x[(size_t)t * DD + i];
        __syncthreads();

        int warp = threadIdx.x >> 5;
        int lane = threadIdx.x & 31;
        const float* wa = wabt + warp * 1024;
        const float* wb = wabt + 8192 + warp * 1024;

        float sa = 0.f, sb = 0.f;
#pragma unroll 4
        for (int kk = lane; kk < DD; kk += 32) {
            float xv = xs[kk];
            sa = fmaf(xv, wa[kk], sa);
            sb = fmaf(xv, wb[kk], sb);
        }
#pragma unroll
        for (int off = 16; off > 0; off >>= 1) {
            sa += __shfl_xor_sync(0xffffffffu, sa, off);
            sb += __shfl_xor_sync(0xffffffffu, sb, off);
        }
        if (lane == 0) {
            float z  = sa + dt_bias[warp];
            float sp = (z > 20.f) ? z : log1pf(expf(z));
            float alpha = expf(-expf(A_log[warp]) * sp);
            float beta  = 1.f + tanh_ap(0.5f * sb);   // 2*sigmoid(sb)
            *(float2*)(abcd + (size_t)(t * HH + warp) * 4) = make_float2(alpha, beta);
        }
    } else if (bid < FB_AB + FB_CQ) {
        do_conv_l2(proj + QO, conv_q, qc, bid - FB_AB);
    } else if (bid < FB_AB + FB_CQ + FB_CK) {
        do_conv_l2(proj + KO, conv_k, kc, bid - FB_AB - FB_CQ);
    } else {
        // conv_v, 4 timesteps per thread
        int idx = (bid - FB_AB - FB_CQ - FB_CK) * 256 + threadIdx.x;  // < NTOK/4*VALD
        int c  = idx % VALD;
        int qq = idx / VALD;                 // 0 .. NTOK/4-1
        int b  = qq / (TSEQ / 4);
        int t0 = (qq % (TSEQ / 4)) * 4;

        const float* base = proj + VO + ((size_t)(b * TSEQ + t0)) * PS + c;

        float xbuf[7];
#pragma unroll
        for (int j = 0; j < 7; j++) {
            int tt = t0 + j - 3;
            xbuf[j] = (tt >= 0) ? base[(ptrdiff_t)(j - 3) * PS] : 0.f;
        }
        float w0 = conv_v[c * KS + 0], w1 = conv_v[c * KS + 1];
        float w2 = conv_v[c * KS + 2], w3 = conv_v[c * KS + 3];

#pragma unroll
        for (int r = 0; r < 4; r++) {
            float acc = 0.f;
            acc = fmaf(w0, xbuf[r],     acc);
            acc = fmaf(w1, xbuf[r + 1], acc);
            acc = fmaf(w2, xbuf[r + 2], acc);
            acc = fmaf(w3, xbuf[r + 3], acc);
            vc[(size_t)(b * TSEQ + t0 + r) * VALD + c] = silu_fast(acc);
        }
    }
}

// ---------------------------------------------------------------------------
// ckd kernel (launch 4): c_t = k_t.k_{t+1} (0 at seq end), d_t = k_t.q_t
// ---------------------------------------------------------------------------
__global__ void __launch_bounds__(256) ckd_kernel(
    const float* __restrict__ qc, const float* __restrict__ kc,
    float* __restrict__ abcd)
{
    int gw   = (blockIdx.x * 256 + threadIdx.x) >> 5;   // bt*HH + h
    int lane = threadIdx.x & 31;
    int h    = gw & 7;
    int bt   = gw >> 3;
    int t    = bt & (TSEQ - 1);

    const float* kp = kc + (size_t)bt * KEYD + h * KDIM + lane * 4;
    const float* qp = qc + (size_t)bt * KEYD + h * KDIM + lane * 4;
    float4 kt = *(const float4*)kp;
    float4 qt = *(const float4*)qp;
    float4 kn = make_float4(0.f, 0.f, 0.f, 0.f);
    if (t < TSEQ - 1) kn = *(const float4*)(kp + KEYD);

    float c = kt.x * kn.x + kt.y * kn.y + kt.z * kn.z + kt.w * kn.w;
    float d = kt.x * qt.x + kt.y * qt.y + kt.z * qt.z + kt.w * qt.w;
#pragma unroll
    for (int off = 16; off > 0; off >>= 1) {
        c += __shfl_xor_sync(0xffffffffu, c, off);
        d += __shfl_xor_sync(0xffffffffu, d, off);
    }
    if (lane == 0)
        *(float2*)(abcd + (size_t)gw * 4 + 2) = make_float2(c, d);
}

// ---------------------------------------------------------------------------
// Recurrent delta-rule scan (launch 5): lookahead-1 algebra + packed f32x2
// state + cp.async double-buffered smem staging (CH=16 timesteps/chunk).
// ---------------------------------------------------------------------------
#define CH     16
#define NCH    (TSEQ / CH)     // 128
#define ROW_W  160             // words per padded k/q row (8 * 20)
#define ROW_B  (ROW_W * 4)     // 640 bytes

__global__ void __launch_bounds__(256) scan_kernel(
    const float* __restrict__ q, const float* __restrict__ k,
    const float* __restrict__ v, const float* __restrict__ abcd,
    float* __restrict__ o)
{
    __shared__ __align__(16) float sk [2][(CH + 1) * ROW_W];
    __shared__ __align__(16) float sq [2][CH * ROW_W];
    __shared__ __align__(16) float sv [2][CH * 32];
    __shared__ __align__(16) float ssc[2][CH * 4];

    int bid  = blockIdx.x;
    int vblk = bid & 7;
    int h    = (bid >> 3) & 7;
    int b    = bid >> 6;

    int tid   = threadIdx.x;
    int warp  = tid >> 5;
    int lane  = tid & 31;
    int rowid = lane & 3;
    int ksub  = lane >> 2;
    int vloc  = warp * 4 + rowid;           // 0..31

    const float* kg = k + (size_t)(b * TSEQ) * KEYD + h * KDIM;
    const float* qg = q + (size_t)(b * TSEQ) * KEYD + h * KDIM;
    const float* vg = v + (size_t)(b * TSEQ) * VALD + h * VDIM + vblk * 32;
    const float* sg = abcd + (size_t)(b * TSEQ) * (HH * 4) + h * 4;
    float*       og = o + (size_t)(b * TSEQ) * VALD + h * VDIM + vblk * 32 + vloc;

    uint32_t skb  = (uint32_t)__cvta_generic_to_shared(&sk[0][0]);
    uint32_t sqb  = (uint32_t)__cvta_generic_to_shared(&sq[0][0]);
    uint32_t svb  = (uint32_t)__cvta_generic_to_shared(&sv[0][0]);
    uint32_t sscb = (uint32_t)__cvta_generic_to_shared(&ssc[0][0]);
    const uint32_t SKBUF  = (CH + 1) * ROW_B;
    const uint32_t SQBUF  = CH * ROW_B;
    const uint32_t SVBUF  = CH * 32 * 4;
    const uint32_t SSCBUF = CH * 16;

#define ISSUE_CHUNK(p, base)                                                   \
    {                                                                          \
        uint32_t kb = skb + (uint32_t)(p) * SKBUF;                             \
        _Pragma("unroll")                                                      \
        for (int pass = 0; pass < 3; pass++) {                                 \
            int f = tid + pass * 256;                                          \
            if (f < (CH + 1) * 32) {                                           \
                int row = f >> 5, m = f & 31;                                  \
                int t = (base) + row; t = t < TSEQ ? t : TSEQ - 1;             \
                cp16(kb + (uint32_t)(row * ROW_B + (m >> 2) * 80 + (m & 3) * 16), \
                     kg + (size_t)t * KEYD + m * 4);                           \
            }                                                                  \
        }                                                                      \
        uint32_t qb = sqb + (uint32_t)(p) * SQBUF;                             \
        _Pragma("unroll")                                                      \
        for (int pass = 0; pass < 2; pass++) {                                 \
            int f = tid + pass * 256;                                          \
            int row = f >> 5, m = f & 31;                                      \
            cp16(qb + (uint32_t)(row * ROW_B + (m >> 2) * 80 + (m & 3) * 16),  \
                 qg + (size_t)((base) + row) * KEYD + m * 4);                  \
        }                                                                      \
        if (tid < 128) {                                                       \
            int row = tid >> 3, j = tid & 7;                                   \
            cp16(svb + (uint32_t)(p) * SVBUF + (uint32_t)((row * 32 + j * 4) * 4), \
                 vg + (size_t)((base) + row) * VALD + j * 4);                  \
        }                                                                      \
        if (tid < CH) {                                                        \
            cp16(sscb + (uint32_t)(p) * SSCBUF + (uint32_t)(tid * 16),         \
                 sg + (size_t)((base) + tid) * (HH * 4));                      \
        }                                                                      \
        asm volatile("cp.async.commit_group;");                                \
    }

    unsigned long long S2[8];
#pragma unroll
    for (int i = 0; i < 8; i++) S2[i] = 0ull;
    float u = 0.f, pa = 0.f, pcoef = 0.f, pcc = 0.f;

    ISSUE_CHUNK(0, 0);

    for (int c = 0; c < NCH; c++) {
        int p = c & 1;
        if (c + 1 < NCH) {
            ISSUE_CHUNK(p ^ 1, (c + 1) * CH);
            asm volatile("cp.async.wait_group 1;");
        } else {
            asm volatile("cp.async.wait_group 0;");
        }
        __syncthreads();

        const char* skp = (const char*)&sk[p][0];
        const char* sqp = (const char*)&sq[p][0];
        const float* svp = &sv[p][0];
        const float* sscp = &ssc[p][0];
        int base = c * CH;

#pragma unroll 4
        for (int tl = 0; tl < CH; tl++) {
            float4 sc = *(const float4*)(sscp + tl * 4);
            float aa = sc.x, bv = sc.y, cc = sc.z, dd = sc.w;
            float vv = svp[tl * 32 + vloc];

            float r    = fmaf(pa, u, pcoef * pcc);
            float coef = fmaf(-(aa * bv), r, bv * vv);

            const char* krow = skp + tl * ROW_B + ksub * 80;
            const char* qrow = sqp + tl * ROW_B + ksub * 80;

            unsigned long long ua = 0ull, wa = 0ull;
#pragma unroll
            for (int i = 0; i < 8; i++) {
                unsigned long long kn = *(const unsigned long long*)(krow + ROW_B + i * 8);
                unsigned long long qq = *(const unsigned long long*)(qrow + i * 8);
                ua = fma2_(S2[i], kn, ua);
                wa = fma2_(S2[i], qq, wa);
            }
            float ul, uh, wl, wh;
            upk2(ul, uh, ua);
            upk2(wl, wh, wa);
            float un = ul + uh, wn = wl + wh;
            un += __shfl_xor_sync(0xffffffffu, un, 4);
            un += __shfl_xor_sync(0xffffffffu, un, 8);
            un += __shfl_xor_sync(0xffffffffu, un, 16);
            wn += __shfl_xor_sync(0xffffffffu, wn, 4);
            wn += __shfl_xor_sync(0xffffffffu, wn, 8);
            wn += __shfl_xor_sync(0xffffffffu, wn, 16);

            unsigned long long aa2 = pk2(aa, aa);
            unsigned long long cf2 = pk2(coef, coef);
#pragma unroll
            for (int i = 0; i < 8; i++) {
                unsigned long long kt = *(const unsigned long long*)(krow + i * 8);
                S2[i] = fma2_(kt, cf2, mul2_(aa2, S2[i]));
            }

            float ov = fmaf(coef, dd, aa * wn);
            if (ksub == 0) og[(size_t)(base + tl) * VALD] = ov;

            u = un; pa = aa; pcoef = coef; pcc = cc;
        }
        __syncthreads();
    }
#undef ISSUE_CHUNK
}

// ---------------------------------------------------------------------------
// RMS norm + weight + SiLU(gate), tf32-rounded output. One warp per (bt,h).
// ---------------------------------------------------------------------------
__global__ void __launch_bounds__(256) normgate_kernel(
    const float* __restrict__ o, const float* __restrict__ proj,
    const float* __restrict__ w, float* __restrict__ y)
{
    int gw   = (blockIdx.x * 256 + threadIdx.x) >> 5;   // bt*H + h
    int lane = threadIdx.x & 31;
    int bt   = gw >> 3, h = gw & 7;

    const float* op = o + (size_t)gw * VDIM + lane * 8;
    const float* gp = proj + GO + (size_t)bt * PS + h * VDIM + lane * 8;
    float*       yp = y + (size_t)gw * VDIM + lane * 8;

    float vals[8];
    *(float4*)(vals)     = *(const float4*)(op);
    *(float4*)(vals + 4) = *(const float4*)(op + 4);

    float ss = 0.f;
#pragma unroll
    for (int i = 0; i < 8; i++) ss = fmaf(vals[i], vals[i], ss);
#pragma unroll
    for (int off = 16; off > 0; off >>= 1)
        ss += __shfl_xor_sync(0xffffffffu, ss, off);
    float rms = rsqrtf(ss * (1.f / VDIM) + 1e-5f);

    float gv[8];
    *(float4*)(gv)     = *(const float4*)(gp);
    *(float4*)(gv + 4) = *(const float4*)(gp + 4);

    float out[8];
#pragma unroll
    for (int i = 0; i < 8; i++) {
        float silu = silu_fast(gv[i]);
        out[i] = tf32round(vals[i] * rms * w[lane * 8 + i] * silu);
    }
    *(float4*)(yp)     = *(float4*)(out);
    *(float4*)(yp + 4) = *(float4*)(out + 4);
}

// ---------------------------------------------------------------------------
// Host launcher
// ---------------------------------------------------------------------------
extern "C" void kernel_launch(void* const* d_in, const int* in_sizes, int n_in,
                              void* d_out, int out_size)
{
    const float* x       = (const float*)d_in[0];
    const float* Wq      = (const float*)d_in[1];
    const float* Wk      = (const float*)d_in[2];
    const float* Wv      = (const float*)d_in[3];
    const float* Wa      = (const float*)d_in[4];
    const float* Wb      = (const float*)d_in[5];
    const float* Wg      = (const float*)d_in[6];
    const float* Wo      = (const float*)d_in[7];
    const float* A_log   = (const float*)d_in[8];
    const float* dt_bias = (const float*)d_in[9];
    const float* conv_q  = (const float*)d_in[10];
    const float* conv_k  = (const float*)d_in[11];
    const float* conv_v  = (const float*)d_in[12];
    const float* o_w     = (const float*)d_in[13];
    float* out = (float*)d_out;

    float* arena = nullptr;
    cudaGetSymbolAddress((void**)&arena, g_arena);

    float* wpack = arena + OFF_WPACK;
    float* xr    = arena + OFF_XR;
    float* wor   = arena + OFF_WOR;
    float* wabt  = arena + OFF_WABT;
    float* proj  = arena + OFF_PROJ;
    float* qc    = arena + OFF_QC;
    float* kc    = arena + OFF_KC;
    float* vc    = arena + OFF_VC;
    float* abcd  = arena + OFF_ABCD;
    float* opre  = arena + OFF_OPRE;
    float* yn    = arena + OFF_YN;

    dim3 blk(256);

    // 1. pack + tf32-round all GEMM operands
    prep_kernel<<<NB_WPACK + NB_AB + NB_XR + NB_WOR, blk>>>(
        Wq, Wk, Wv, Wg, Wa, Wb, Wo, x, wpack, wabt, xr, wor);

    // 2. fused q|k|v|g projection (pre-rounded TF32)
    tf32gemm_kernel<<<dim3(PS / 128, NTOK / 128), blk>>>(xr, wpack, proj, NTOK, PS, DD);

    // 3. fused alpha/beta + convs (tanh-approx SiLU; conv_v 4-t per thread)
    fused_pre_kernel<<<FB_AB + FB_CQ + FB_CK + FB_CV, blk>>>(
        x, proj, wabt, A_log, dt_bias, conv_q, conv_k, conv_v,
        abcd, qc, kc, vc);

    // 4. precompute c = k_t.k_{t+1}, d = k_t.q_t
    ckd_kernel<<<(NTOK * HH) / 8, blk>>>(qc, kc, abcd);

    // 5. recurrent scan (lookahead-1, packed f32x2, smem-staged)
    scan_kernel<<<BB * HH * (VDIM / 32), blk>>>(qc, kc, vc, abcd, opre);

    // 6. rms norm + gate (tanh-approx SiLU, tf32-rounded output)
    normgate_kernel<<<(NTOK * HH) / 8, blk>>>(opre, proj, o_w, yn);

    // 7. output projection (pre-rounded TF32)
    tf32gemm_kernel<<<dim3(DD / 128, NTOK / 128), blk>>>(yn, wor, out, NTOK, DD, VALD);
}